// round 6
// baseline (speedup 1.0000x reference)
#include <cuda_runtime.h>
#include <stdint.h>

// ExtractSearchWindows: out[b,y,x, wy*7+wx, ty*7+tx] = Qpad[b][y+wy+ty][x+wx+tx]
// Qpad = zero-padded (pad=6) image, values = trunc(input) in [0,255). Output f32.
//
// 708 MB f32 stores -> pure store-BW problem. SINGLE launch; block (b,y,uslice)
// of 352 threads: builds 13x204 row table from the L2-resident input, then
// threads 0..342 each own one float4 chunk (descriptor computed in registers)
// and emit 12 coalesced streaming STG.128 (one per x-group).
// grid(384,28), 5 blocks/SM -> W = 10752/740 = 14.53 waves -> 96.9% tail eff.

#define T_ROWS    13
#define T_COLS    208
#define NT        352            // 11 warps; threads 0..342 own chunks
#define SLICE     343            // float4 chunks per block (28 * 343 = 9604)
#define ROW_ELEMS 460992         // 192 * 2401 floats per (b,y) row
#define XG_STRIDE 9604           // float4 stride between x-groups (38416/4)

__global__ __launch_bounds__(NT) void main_k(const float* __restrict__ in,
                                             float* __restrict__ out) {
    __shared__ float Tsh[T_ROWS * T_COLS];

    int rowid = blockIdx.x;              // 0..383 = b*192 + y
    int usl   = blockIdx.y;              // 0..27
    int b   = rowid / 192;
    int y   = rowid - b * 192;
    int tid = threadIdx.x;
    int ubase = usl * SLICE;

    // ---- Prologue A: row table directly from input (pad=6, trunc-to-u8) ----
    // Tsh[r*208 + c] = Qpad[b][y+r][c] for r in [0,13), c in [0,204)
    const float* inb = in + (size_t)b * 192 * 192;
    for (int idx = tid; idx < T_ROWS * 204; idx += NT) {
        int r = idx / 204;
        int c = idx - r * 204;
        int gr = y + r - 6;              // global image row
        int gc = c - 6;                  // global image col
        float v = 0.0f;
        if ((unsigned)gr < 192u && (unsigned)gc < 192u)
            v = (float)__float2uint_rz(inb[gr * 192 + gc]);
        Tsh[r * T_COLS + c] = v;
    }

    // ---- Prologue B: this thread's chunk descriptor, in registers ----
    // Chunk u covers elements [4u,4u+4) of the 38416-elem 16-x region.
    // Element e: xi=e/2401, rr=e%2401 -> w=rr/49 (wy,wx), p=rr%49 (ty,tx);
    // smem offset = (wy+ty)*T_COLS + (xi+wx+tx); runtime adds 16*xg.
    int o0 = 0, o1 = 0, o2 = 0, o3 = 0;
    if (tid < SLICE) {
        int u = ubase + tid;
        int offs[4];
#pragma unroll
        for (int j = 0; j < 4; j++) {
            int e  = 4 * u + j;
            int xi = e / 2401;
            int rr = e - xi * 2401;
            int w  = rr / 49;
            int p  = rr - w * 49;
            int wy = w / 7, wx = w - wy * 7;
            int ty = p / 7, tx = p - ty * 7;
            offs[j] = (wy + ty) * T_COLS + (xi + wx + tx);
        }
        o0 = offs[0]; o1 = offs[1]; o2 = offs[2]; o3 = offs[3];
    }
    __syncthreads();

    // ---- Main store stream: 12 coalesced STG.128 per owning thread ----
    if (tid < SLICE) {
        float4* gp = (float4*)(out + (size_t)rowid * ROW_ELEMS)
                   + (ubase + tid);      // consecutive lanes -> consecutive 16B

#pragma unroll
        for (int xg = 0; xg < 12; xg++) {
            int st = xg * 16;            // +16 smem columns per x-group
            float4 v;
            v.x = Tsh[o0 + st];
            v.y = Tsh[o1 + st];
            v.z = Tsh[o2 + st];
            v.w = Tsh[o3 + st];
            __stcs(gp + (size_t)xg * XG_STRIDE, v);
        }
    }
}

// ---------------------------------------------------------------- launcher

extern "C" void kernel_launch(void* const* d_in, const int* in_sizes, int n_in,
                              void* d_out, int out_size) {
    const float* in = (const float*)d_in[0];
    // d_in[1] = search_range (fixed at 3: cv=7, offset=0 baked into descriptors)

    dim3 grid(384, 28);
    main_k<<<grid, NT>>>(in, (float*)d_out);
}

// round 7
// speedup vs baseline: 1.0939x; 1.0939x over previous
#include <cuda_runtime.h>
#include <stdint.h>

// ExtractSearchWindows: out[b,y,x, wy*7+wx, ty*7+tx] = Qpad[b][y+wy+ty][x+wx+tx]
// Qpad = zero-padded (pad=6) image, values = trunc(input) in [0,255). Output f32.
//
// 708 MB f32 stores -> pure store-BW problem. SINGLE launch; block (b,y,uslice)
// of 512 threads (4 blocks/SM = full 64 warp slots): builds 13x204 row table
// from the L2-resident input + 343 chunk descriptors in smem, then streams
// 343 float4 chunks x 12 x-groups as 343x4 units of 3 STG.128 (u-major lane
// map keeps stores coalesced; per-unit overhead amortized over 3 stores).
// grid(384,28) -> W = 10752/592 = 18.16 waves -> 95.6% tail efficiency.

#define T_ROWS    13
#define T_COLS    208
#define NT        512
#define SLICE     343            // float4 chunks per block (28 * 343 = 9604)
#define NUNITS    (SLICE * 4)    // 1372 (u, xg-triple) units per block
#define ROW_ELEMS 460992         // 192 * 2401 floats per (b,y) row
#define XG_STRIDE 9604           // float4 stride between x-groups (38416/4)

__global__ __launch_bounds__(NT) void main_k(const float* __restrict__ in,
                                             float* __restrict__ out) {
    __shared__ float   Tsh[T_ROWS * T_COLS];
    __shared__ ushort4 Dsh[SLICE];

    int rowid = blockIdx.x;              // 0..383 = b*192 + y
    int usl   = blockIdx.y;              // 0..27
    int b   = rowid / 192;
    int y   = rowid - b * 192;
    int tid = threadIdx.x;
    int ubase = usl * SLICE;

    // ---- Prologue A: row table directly from input (pad=6, trunc-to-u8) ----
    // Tsh[r*208 + c] = Qpad[b][y+r][c] for r in [0,13), c in [0,204)
    const float* inb = in + (size_t)b * 192 * 192;
    for (int idx = tid; idx < T_ROWS * 204; idx += NT) {
        int r = idx / 204;
        int c = idx - r * 204;
        int gr = y + r - 6;              // global image row
        int gc = c - 6;                  // global image col
        float v = 0.0f;
        if ((unsigned)gr < 192u && (unsigned)gc < 192u)
            v = (float)__float2uint_rz(inb[gr * 192 + gc]);
        Tsh[r * T_COLS + c] = v;
    }

    // ---- Prologue B: per-chunk descriptors for this slice ----
    // Chunk u covers elements [4u,4u+4) of the 38416-elem 16-x region.
    // Element e: xi=e/2401, rr=e%2401 -> w=rr/49 (wy,wx), p=rr%49 (ty,tx);
    // smem offset = (wy+ty)*T_COLS + (xi+wx+tx); runtime adds 16*xg.
    if (tid < SLICE) {
        int u = ubase + tid;
        unsigned short off[4];
#pragma unroll
        for (int j = 0; j < 4; j++) {
            int e  = 4 * u + j;
            int xi = e / 2401;
            int rr = e - xi * 2401;
            int w  = rr / 49;
            int p  = rr - w * 49;
            int wy = w / 7, wx = w - wy * 7;
            int ty = p / 7, tx = p - ty * 7;
            off[j] = (unsigned short)((wy + ty) * T_COLS + (xi + wx + tx));
        }
        Dsh[tid] = make_ushort4(off[0], off[1], off[2], off[3]);
    }
    __syncthreads();

    // ---- Main store stream: units of 3 coalesced STG.128 ----
    float4* rowout4 = (float4*)(out + (size_t)rowid * ROW_ELEMS);

#pragma unroll 1
    for (int idx = tid; idx < NUNITS; idx += NT) {
        int xgp = idx / SLICE;           // 0..3 (triple of x-groups)
        int uu  = idx - xgp * SLICE;     // 0..342, u-major: lanes coalesced
        ushort4 d = Dsh[uu];
        int xg0 = 3 * xgp;
        int st0 = xg0 * 16;

        // Base pointers per unit; inner loop uses immediate offsets (j*16)
        const float* p0 = Tsh + d.x + st0;
        const float* p1 = Tsh + d.y + st0;
        const float* p2 = Tsh + d.z + st0;
        const float* p3 = Tsh + d.w + st0;

        float4* gp = rowout4 + (ubase + uu) + (size_t)xg0 * XG_STRIDE;

#pragma unroll
        for (int j = 0; j < 3; j++) {
            float4 v;
            v.x = p0[j * 16];
            v.y = p1[j * 16];
            v.z = p2[j * 16];
            v.w = p3[j * 16];
            __stcs(gp + (size_t)j * XG_STRIDE, v);
        }
    }
}

// ---------------------------------------------------------------- launcher

extern "C" void kernel_launch(void* const* d_in, const int* in_sizes, int n_in,
                              void* d_out, int out_size) {
    const float* in = (const float*)d_in[0];
    // d_in[1] = search_range (fixed at 3: cv=7, offset=0 baked into descriptors)

    dim3 grid(384, 28);
    main_k<<<grid, NT>>>(in, (float*)d_out);
}